// round 13
// baseline (speedup 1.0000x reference)
#include <cuda_runtime.h>

#define B   32
#define C   512
#define HW  1024
#define T   1025
#define NH  8
#define CH  64
#define SCALE2 0.125f   // (1/64^{0.25})^2 = 1/8

typedef unsigned long long u64;

// ---------------------------------------------------------------------------
// Scratch (allocation-free rules -> __device__ globals)
__device__ float g_x0 [B * C];
__device__ float g_q0 [B * C];
__device__ float g_k0 [B * C];
__device__ float g_qw [B * NH * C];
__device__ float g_l0 [B * NH];          // logit at t=0
__device__ float g_mc [B * 4 * NH];      // chunk max
__device__ float g_sc [B * 4 * NH];      // chunk expsum
__device__ float g_yp [B * 4 * NH * C];  // chunk y-partials
__device__ float g_y  [B * NH * C];
__device__ float g_a  [B * C];
__device__ float g_poss[C * HW];         // pos shifted: [c][t-1]

__device__ unsigned g_count = 0;
__device__ volatile unsigned g_sense = 0;

// f32 warp reductions via butterfly shuffle (result valid in ALL lanes).
// (redux.sync.f32 does not exist on sm_100 -- integer only.)
__device__ __forceinline__ float wredux(float v) {
    #pragma unroll
    for (int o = 16; o; o >>= 1) v += __shfl_xor_sync(0xffffffffu, v, o);
    return v;
}
__device__ __forceinline__ float wredux_max(float v) {
    #pragma unroll
    for (int o = 16; o; o >>= 1) v = fmaxf(v, __shfl_xor_sync(0xffffffffu, v, o));
    return v;
}

// ---- packed f32x2 helpers (Blackwell FFMA2 path, PTX-only) ----------------
__device__ __forceinline__ u64 pack2(float lo, float hi) {
    u64 r; asm("mov.b64 %0, {%1, %2};" : "=l"(r) : "f"(lo), "f"(hi)); return r;
}
__device__ __forceinline__ u64 add2(u64 a, u64 b) {
    u64 r; asm("add.rn.f32x2 %0, %1, %2;" : "=l"(r) : "l"(a), "l"(b)); return r;
}
__device__ __forceinline__ void fma2(u64& d, u64 a, u64 b) {
    asm("fma.rn.f32x2 %0, %1, %2, %0;" : "+l"(d) : "l"(a), "l"(b));
}
__device__ __forceinline__ float2 unpack2(u64 v) {
    float2 f; asm("mov.b64 {%0, %1}, %2;" : "=f"(f.x), "=f"(f.y) : "l"(v)); return f;
}

// ---------------------------------------------------------------------------
__global__ void __launch_bounds__(1024, 1)
attn_pool_persistent(const float* __restrict__ x,
                     const float* __restrict__ pos,
                     const float* __restrict__ wqkv,
                     const float* __restrict__ bqkv,
                     const float* __restrict__ wc,
                     const float* __restrict__ bc,
                     float* __restrict__ out) {
    __shared__ __align__(16) float buf[12288];   // 48 KB phase-shared scratch

    const int tid  = threadIdx.x;
    const int warp = tid >> 5, lane = tid & 31;
    const int bid  = blockIdx.x;
    const int NB   = gridDim.x;
    const int NW   = NB * 32;
    const int gw   = bid * 32 + warp;

    unsigned sense = g_sense;

    auto gbar = [&]() {
        __syncthreads();
        if (tid == 0) {
            unsigned s = sense ^ 1u;
            __threadfence();
            if (atomicAdd(&g_count, 1u) == (unsigned)NB - 1u) {
                g_count = 0;
                __threadfence();
                g_sense = s;
            } else {
                while (g_sense != s) { }
            }
            __threadfence();
        }
        __syncthreads();
        sense ^= 1u;
    };

    // ---- Phase 1: spatial mean -> x0; build shifted pos table --------------
    for (int row = gw; row < B * C; row += NW) {
        const float4* p = (const float4*)(x + (size_t)row * HW);
        float s = 0.0f;
        #pragma unroll
        for (int k = 0; k < 8; k++) {
            float4 v = p[lane + 32 * k];
            s += v.x + v.y + v.z + v.w;
        }
        s = wredux(s);
        if (lane == 0)
            g_x0[row] = s * (1.0f / HW) + pos[(size_t)(row & (C - 1)) * T];
    }
    for (int i = bid * 1024 + tid; i < C * HW; i += NB * 1024) {
        int c = i >> 10, j = i & 1023;
        g_poss[i] = pos[(size_t)c * T + j + 1];
    }
    gbar();

    // ---- Phase 2: q0s & k0.  Warp per (qk, o, b-group-of-8). ---------------
    for (int it = gw; it < 2 * C * 4; it += NW) {
        int qk = it >> 11, rem = it & 2047;
        int o = rem >> 2, bg = rem & 3;
        const float4* w = (const float4*)(wqkv + (size_t)(qk * C + o) * C);
        float4 wr[4];
        #pragma unroll
        for (int k = 0; k < 4; k++) wr[k] = w[lane + 32 * k];
        float bq = bqkv[o];
        #pragma unroll
        for (int j = 0; j < 8; j++) {
            int b = bg * 8 + j;
            const float4* xv = (const float4*)(g_x0 + (size_t)b * C);
            float acc = 0.0f;
            #pragma unroll
            for (int k = 0; k < 4; k++) {
                float4 d = xv[lane + 32 * k];
                acc += wr[k].x * d.x + wr[k].y * d.y + wr[k].z * d.z + wr[k].w * d.w;
            }
            acc = wredux(acc);
            if (lane == 0) {
                if (qk == 0) g_q0[b * C + o] = SCALE2 * (acc + bq);
                else         g_k0[b * C + o] = acc;
            }
        }
    }
    gbar();

    // ---- Phase 3: qw fold (thread per output, coalesced) + logit0 ----------
    for (int idx = bid * 1024 + tid; idx < B * NH * C; idx += NB * 1024) {
        int b = idx >> 12, rem = idx & 4095, h = rem >> 9, ci = rem & (C - 1);
        const float* wk = wqkv + (size_t)(C + h * CH) * C + ci;
        const float* q  = g_q0 + (size_t)b * C + h * CH;
        float acc = 0.0f;
        #pragma unroll 8
        for (int ch = 0; ch < CH; ch++) acc += q[ch] * wk[(size_t)ch * C];
        g_qw[idx] = acc;
    }
    for (int it = gw; it < B * NH; it += NW) {
        int b = it >> 3, h = it & 7;
        const float* q = g_q0 + (size_t)b * C + h * CH;
        const float* k = g_k0 + (size_t)b * C + h * CH;
        float acc = q[lane] * k[lane] + q[lane + 32] * k[lane + 32];
        acc = wredux(acc);
        if (lane == 0) g_l0[it] = acc;
    }
    gbar();

    // ---- Phase 4F: fused logits + chunk softmax + y-partials ---------------
    // Unit = (b, 256-t chunk); 128 units, balanced 1/block.
    for (int u = bid; u < B * 4; u += NB) {
        int b  = u >> 2;
        int chunk = u & 3;
        int t0 = chunk * 256;

        // stage 0: qw -> smem, transposed [ci*8 + h]  (buf[0..4096])
        for (int i = tid; i < NH * C; i += 1024) {
            int h = i >> 9, ci = i & (C - 1);
            buf[ci * 8 + h] = g_qw[(size_t)b * NH * C + i];
        }
        __syncthreads();

        // stage 1: logits.  8 slabs x 128 threads; thread owns 2 t.
        int tl = tid & 127, slab = tid >> 7;
        {
            int t = t0 + 2 * tl;
            const float2* xb = (const float2*)(x + (size_t)b * C * HW + t);
            const float2* pb = (const float2*)(g_poss + t);
            u64 a0[4], a1[4];
            #pragma unroll
            for (int i = 0; i < 4; i++) { a0[i] = 0ull; a1[i] = 0ull; }
            int ci0 = slab * 64;
            #pragma unroll 4
            for (int cc = 0; cc < 64; cc++) {
                int ci = ci0 + cc;
                float2 xv = xb[(size_t)ci * (HW / 2)];
                float2 pv = pb[(size_t)ci * (HW / 2)];
                float v0 = xv.x + pv.x, v1 = xv.y + pv.y;
                u64 s0 = pack2(v0, v0), s1 = pack2(v1, v1);
                const float4* wv = (const float4*)&buf[ci * 8];
                float4 w0 = wv[0], w1 = wv[1];
                u64 wp0 = pack2(w0.x, w0.y), wp1 = pack2(w0.z, w0.w);
                u64 wp2 = pack2(w1.x, w1.y), wp3 = pack2(w1.z, w1.w);
                fma2(a0[0], wp0, s0); fma2(a0[1], wp1, s0);
                fma2(a0[2], wp2, s0); fma2(a0[3], wp3, s0);
                fma2(a1[0], wp0, s1); fma2(a1[1], wp1, s1);
                fma2(a1[2], wp2, s1); fma2(a1[3], wp3, s1);
            }
            float* red = buf + 4096;             // 8192 floats, conflict-free
            #pragma unroll
            for (int par = 0; par < 2; par++) {
                __syncthreads();
                #pragma unroll
                for (int hp = 0; hp < 4; hp++) {
                    float2 f = unpack2(par == 0 ? a0[hp] : a1[hp]);
                    red[(slab * 8 + hp * 2)     * 128 + tl] = f.x;
                    red[(slab * 8 + hp * 2 + 1) * 128 + tl] = f.y;
                }
                __syncthreads();
                int h2 = tid >> 7, tl2 = tid & 127;
                float s = 0.0f;
                #pragma unroll
                for (int q = 0; q < 8; q++) s += red[(q * 8 + h2) * 128 + tl2];
                // logits live in smem only: slog[h][t_local] at buf[0..2048]
                buf[h2 * 256 + 2 * tl2 + par] = s;
            }
        }
        __syncthreads();

        // stage 2: chunk softmax on slog (in place).  h-group = 128 threads.
        {
            int h = tid >> 7, i = tid & 127;
            float v0 = buf[h * 256 + i], v1 = buf[h * 256 + i + 128];
            float m = wredux_max(fmaxf(v0, v1));
            if (lane == 0) buf[2048 + warp] = m;   // per-warp maxes
            __syncthreads();
            float M = fmaxf(fmaxf(buf[2048 + h * 4],     buf[2048 + h * 4 + 1]),
                            fmaxf(buf[2048 + h * 4 + 2], buf[2048 + h * 4 + 3]));
            float e0 = __expf(v0 - M), e1 = __expf(v1 - M);
            float s = wredux(e0 + e1);
            buf[h * 256 + i]       = e0;           // probs (unnormalized)
            buf[h * 256 + i + 128] = e1;
            if (lane == 0) buf[2080 + warp] = s;   // per-warp sums
            __syncthreads();
            if (tid < NH) {
                float sc = buf[2080 + tid * 4]     + buf[2080 + tid * 4 + 1]
                         + buf[2080 + tid * 4 + 2] + buf[2080 + tid * 4 + 3];
                float Mh = fmaxf(fmaxf(buf[2048 + tid * 4],     buf[2048 + tid * 4 + 1]),
                                 fmaxf(buf[2048 + tid * 4 + 2], buf[2048 + tid * 4 + 3]));
                g_sc[(b * 4 + chunk) * NH + tid] = sc;
                g_mc[(b * 4 + chunk) * NH + tid] = Mh;
            }
        }
        __syncthreads();

        // stage 3: y-partials.  Warp owns 2 ci; probs from slog (smem).
        #pragma unroll 1
        for (int r = 0; r < 8; r++) {
            int ci0 = r * 64 + warp * 2;
            const float4* xr0 = (const float4*)(x + ((size_t)b * C + ci0) * HW + t0);
            const float4* xr1 = (const float4*)(x + ((size_t)b * C + ci0 + 1) * HW + t0);
            const float4* pr0 = (const float4*)(g_poss + (size_t)ci0 * HW + t0);
            const float4* pr1 = (const float4*)(g_poss + (size_t)(ci0 + 1) * HW + t0);
            u64 acca[8], accc[8];
            #pragma unroll
            for (int h = 0; h < 8; h++) { acca[h] = 0ull; accc[h] = 0ull; }
            #pragma unroll
            for (int k = 0; k < 2; k++) {
                int i4 = lane + 32 * k;
                float4 xa = xr0[i4], pa = pr0[i4];
                float4 xc = xr1[i4], pc = pr1[i4];
                u64 va01 = add2(pack2(xa.x, xa.y), pack2(pa.x, pa.y));
                u64 va23 = add2(pack2(xa.z, xa.w), pack2(pa.z, pa.w));
                u64 vc01 = add2(pack2(xc.x, xc.y), pack2(pc.x, pc.y));
                u64 vc23 = add2(pack2(xc.z, xc.w), pack2(pc.z, pc.w));
                #pragma unroll
                for (int h = 0; h < 8; h++) {
                    float4 pv = ((const float4*)buf)[h * 64 + i4];
                    u64 p01 = pack2(pv.x, pv.y), p23 = pack2(pv.z, pv.w);
                    fma2(acca[h], p01, va01);
                    fma2(acca[h], p23, va23);
                    fma2(accc[h], p01, vc01);
                    fma2(accc[h], p23, vc23);
                }
            }
            #pragma unroll
            for (int h = 0; h < 8; h++) {
                float2 fa = unpack2(acca[h]);
                float2 fc = unpack2(accc[h]);
                float r0 = wredux(fa.x + fa.y);
                float r1 = wredux(fc.x + fc.y);
                if (lane == 0) {
                    size_t o = ((size_t)(b * 4 + chunk) * NH + h) * C + ci0;
                    g_yp[o]     = r0;
                    g_yp[o + 1] = r1;
                }
            }
        }
        __syncthreads();
    }
    gbar();

    // ---- Phase MG: merge chunk partials + t=0 term -> g_y ------------------
    {
        // prelude: per-(b,h) coefficients in smem (redundant per block, cheap)
        if (tid < B * NH) {
            int b = tid >> 3, h = tid & 7;
            float m0 = g_mc[(b * 4 + 0) * NH + h], m1 = g_mc[(b * 4 + 1) * NH + h];
            float m2 = g_mc[(b * 4 + 2) * NH + h], m3 = g_mc[(b * 4 + 3) * NH + h];
            float s0 = g_sc[(b * 4 + 0) * NH + h], s1 = g_sc[(b * 4 + 1) * NH + h];
            float s2 = g_sc[(b * 4 + 2) * NH + h], s3 = g_sc[(b * 4 + 3) * NH + h];
            float l0 = g_l0[b * NH + h];
            float M = fmaxf(fmaxf(fmaxf(m0, m1), fmaxf(m2, m3)), l0);
            float w0 = __expf(m0 - M), w1 = __expf(m1 - M);
            float w2 = __expf(m2 - M), w3 = __expf(m3 - M);
            float wl = __expf(l0 - M);
            float inv = 1.0f / (w0 * s0 + w1 * s1 + w2 * s2 + w3 * s3 + wl);
            buf[tid * 8 + 0] = w0 * inv;
            buf[tid * 8 + 1] = w1 * inv;
            buf[tid * 8 + 2] = w2 * inv;
            buf[tid * 8 + 3] = w3 * inv;
            buf[tid * 8 + 4] = wl * inv;
        }
        __syncthreads();
        for (int idx = bid * 1024 + tid; idx < B * NH * C; idx += NB * 1024) {
            int bh = idx >> 9, ci = idx & (C - 1);
            int b = bh >> 3, h = bh & 7;
            float y = buf[bh * 8 + 4] * g_x0[(size_t)b * C + ci];
            #pragma unroll
            for (int c = 0; c < 4; c++)
                y += buf[bh * 8 + c] *
                     g_yp[((size_t)(b * 4 + c) * NH + h) * C + ci];
            g_y[(size_t)bh * C + ci] = y;
        }
    }
    gbar();

    // ---- Phase 7: attn = b_v + W_v . y.  Warp per (c, b-group-of-8). -------
    for (int it = gw; it < C * 4; it += NW) {
        int c = it >> 2, bg = it & 3, h = c >> 6;
        const float4* w = (const float4*)(wqkv + (size_t)(2 * C + c) * C);
        float4 wr[4];
        #pragma unroll
        for (int k = 0; k < 4; k++) wr[k] = w[lane + 32 * k];
        float bv = bqkv[2 * C + c];
        #pragma unroll
        for (int j = 0; j < 8; j++) {
            int b = bg * 8 + j;
            const float4* y = (const float4*)(g_y + ((size_t)b * NH + h) * C);
            float acc = 0.0f;
            #pragma unroll
            for (int k = 0; k < 4; k++) {
                float4 d = y[lane + 32 * k];
                acc += wr[k].x * d.x + wr[k].y * d.y + wr[k].z * d.z + wr[k].w * d.w;
            }
            acc = wredux(acc);
            if (lane == 0) g_a[b * C + c] = acc + bv;
        }
    }
    gbar();

    // ---- Phase 8: out = b_c + W_c . attn.  Warp per (o, b-group-of-8). -----
    for (int it = gw; it < C * 4; it += NW) {
        int o = it >> 2, bg = it & 3;
        const float4* w = (const float4*)(wc + (size_t)o * C);
        float4 wr[4];
        #pragma unroll
        for (int k = 0; k < 4; k++) wr[k] = w[lane + 32 * k];
        float bo = bc[o];
        #pragma unroll
        for (int j = 0; j < 8; j++) {
            int b = bg * 8 + j;
            const float4* a = (const float4*)(g_a + (size_t)b * C);
            float acc = 0.0f;
            #pragma unroll
            for (int k = 0; k < 4; k++) {
                float4 d = a[lane + 32 * k];
                acc += wr[k].x * d.x + wr[k].y * d.y + wr[k].z * d.z + wr[k].w * d.w;
            }
            acc = wredux(acc);
            if (lane == 0) out[b * C + o] = acc + bo;
        }
    }
}

// ---------------------------------------------------------------------------
extern "C" void kernel_launch(void* const* d_in, const int* in_sizes, int n_in,
                              void* d_out, int out_size) {
    const float* x    = (const float*)d_in[0];
    const float* pos  = (const float*)d_in[1];
    const float* wqkv = (const float*)d_in[2];
    const float* bqkv = (const float*)d_in[3];
    const float* wc   = (const float*)d_in[4];
    const float* bc   = (const float*)d_in[5];
    float* out = (float*)d_out;

    int nsm = 0;
    cudaDeviceGetAttribute(&nsm, cudaDevAttrMultiProcessorCount, 0);
    if (nsm <= 0) nsm = 148;
    attn_pool_persistent<<<nsm, 1024>>>(x, pos, wqkv, bqkv, wc, bc, out);
}

// round 15
// speedup vs baseline: 1.4606x; 1.4606x over previous
#include <cuda_runtime.h>

#define B   32
#define C   512
#define HW  1024
#define T   1025
#define NH  8
#define CH  64
#define SCALE2 0.125f   // (1/64^{0.25})^2 = 1/8

typedef unsigned long long u64;

// ---------------------------------------------------------------------------
// Scratch (allocation-free rules -> __device__ globals)
__device__ float g_x0 [B * C];
__device__ float g_q0 [B * C];
__device__ float g_k0 [B * C];
__device__ float g_qw [B * NH * C];
__device__ float g_p  [B * NH * T];
__device__ float g_ps [B * NH * HW];    // probs, shifted: [b][h][t-1]
__device__ float g_p0 [B * NH];
__device__ float g_y  [B * NH * C];
__device__ float g_a  [B * C];
__device__ float g_poss[C * HW];        // pos shifted: [c][t-1]

__device__ unsigned g_count = 0;
__device__ volatile unsigned g_sense = 0;

__device__ __forceinline__ float wred(float v) {
    #pragma unroll
    for (int o = 16; o; o >>= 1) v += __shfl_xor_sync(0xffffffffu, v, o);
    return v;
}

// ---- packed f32x2 helpers (Blackwell FFMA2 path, PTX-only) ----------------
__device__ __forceinline__ u64 pack2(float lo, float hi) {
    u64 r; asm("mov.b64 %0, {%1, %2};" : "=l"(r) : "f"(lo), "f"(hi)); return r;
}
__device__ __forceinline__ u64 add2(u64 a, u64 b) {
    u64 r; asm("add.rn.f32x2 %0, %1, %2;" : "=l"(r) : "l"(a), "l"(b)); return r;
}
__device__ __forceinline__ void fma2(u64& d, u64 a, u64 b) {
    asm("fma.rn.f32x2 %0, %1, %2, %0;" : "+l"(d) : "l"(a), "l"(b));
}
__device__ __forceinline__ float2 unpack2(u64 v) {
    float2 f; asm("mov.b64 {%0, %1}, %2;" : "=f"(f.x), "=f"(f.y) : "l"(v)); return f;
}

// Grid barrier used INSIDE each persistent kernel (1 block/SM guaranteed).
#define GBAR()                                                              \
    do {                                                                    \
        __syncthreads();                                                    \
        if (threadIdx.x == 0) {                                             \
            unsigned s_ = sense ^ 1u;                                       \
            __threadfence();                                                \
            if (atomicAdd(&g_count, 1u) == (unsigned)gridDim.x - 1u) {      \
                g_count = 0;                                                \
                __threadfence();                                            \
                g_sense = s_;                                               \
            } else {                                                        \
                while (g_sense != s_) { }                                   \
            }                                                               \
            __threadfence();                                                \
        }                                                                   \
        __syncthreads();                                                    \
        sense ^= 1u;                                                        \
    } while (0)

// ===========================================================================
// K1 = P1 (mean + poss) | P2 (q0/k0) | P3 (qw fold + logit0)
// ===========================================================================
__global__ void __launch_bounds__(1024, 1)
k_front(const float* __restrict__ x, const float* __restrict__ pos,
        const float* __restrict__ wqkv, const float* __restrict__ bqkv) {
    const int tid = threadIdx.x;
    const int warp = tid >> 5, lane = tid & 31;
    const int bid = blockIdx.x, NB = gridDim.x;
    const int NW = NB * 32, gw = bid * 32 + warp;
    unsigned sense = g_sense;

    // ---- Phase 1 -----------------------------------------------------------
    for (int row = gw; row < B * C; row += NW) {
        const float4* p = (const float4*)(x + (size_t)row * HW);
        float s = 0.0f;
        #pragma unroll
        for (int k = 0; k < 8; k++) {
            float4 v = p[lane + 32 * k];
            s += v.x + v.y + v.z + v.w;
        }
        s = wred(s);
        if (lane == 0)
            g_x0[row] = s * (1.0f / HW) + pos[(size_t)(row & (C - 1)) * T];
    }
    for (int i = bid * 1024 + tid; i < C * HW; i += NB * 1024) {
        int c = i >> 10, j = i & 1023;
        g_poss[i] = pos[(size_t)c * T + j + 1];
    }
    GBAR();

    // ---- Phase 2 -----------------------------------------------------------
    for (int it = gw; it < 2 * C * 4; it += NW) {
        int qk = it >> 11, rem = it & 2047;
        int o = rem >> 2, bg = rem & 3;
        const float4* w = (const float4*)(wqkv + (size_t)(qk * C + o) * C);
        float4 wr[4];
        #pragma unroll
        for (int k = 0; k < 4; k++) wr[k] = w[lane + 32 * k];
        float bq = bqkv[o];
        #pragma unroll
        for (int j = 0; j < 8; j++) {
            int b = bg * 8 + j;
            const float4* xv = (const float4*)(g_x0 + (size_t)b * C);
            float acc = 0.0f;
            #pragma unroll
            for (int k = 0; k < 4; k++) {
                float4 d = xv[lane + 32 * k];
                acc += wr[k].x * d.x + wr[k].y * d.y + wr[k].z * d.z + wr[k].w * d.w;
            }
            acc = wred(acc);
            if (lane == 0) {
                if (qk == 0) g_q0[b * C + o] = SCALE2 * (acc + bq);
                else         g_k0[b * C + o] = acc;
            }
        }
    }
    GBAR();

    // ---- Phase 3 -----------------------------------------------------------
    for (int idx = bid * 1024 + tid; idx < B * NH * C; idx += NB * 1024) {
        int b = idx >> 12, rem = idx & 4095, h = rem >> 9, ci = rem & (C - 1);
        const float* wk = wqkv + (size_t)(C + h * CH) * C + ci;
        const float* q  = g_q0 + (size_t)b * C + h * CH;
        float acc = 0.0f;
        #pragma unroll 8
        for (int ch = 0; ch < CH; ch++) acc += q[ch] * wk[(size_t)ch * C];
        g_qw[idx] = acc;
    }
    for (int it = gw; it < B * NH; it += NW) {
        int b = it >> 3, h = it & 7;
        const float* q = g_q0 + (size_t)b * C + h * CH;
        const float* k = g_k0 + (size_t)b * C + h * CH;
        float acc = q[lane] * k[lane] + q[lane + 32] * k[lane + 32];
        acc = wred(acc);
        if (lane == 0) g_p[(size_t)it * T] = acc;
    }
}

// ===========================================================================
// K2 = P4 (logits, conflict-free reduction) | P5 (softmax -> shifted probs)
// ===========================================================================
__global__ void __launch_bounds__(1024, 1)
k_mid(const float* __restrict__ x) {
    __shared__ __align__(16) float buf[12288];
    const int tid = threadIdx.x;
    const int warp = tid >> 5, lane = tid & 31;
    const int bid = blockIdx.x, NB = gridDim.x;
    unsigned sense = g_sense;

    // ---- Phase 4 -----------------------------------------------------------
    for (int u = bid; u < B * 4; u += NB) {
        int b  = u >> 2;
        int t0 = (u & 3) * 256;
        int tl = tid & 127, slab = tid >> 7;
        for (int i = tid; i < NH * C; i += 1024) {
            int h = i >> 9, ci = i & (C - 1);
            buf[ci * 8 + h] = g_qw[(size_t)b * NH * C + i];
        }
        __syncthreads();

        int t = t0 + 2 * tl;
        const float2* xb = (const float2*)(x + (size_t)b * C * HW + t);
        const float2* pb = (const float2*)(g_poss + t);
        u64 a0[4], a1[4];
        #pragma unroll
        for (int i = 0; i < 4; i++) { a0[i] = 0ull; a1[i] = 0ull; }
        int ci0 = slab * 64;
        #pragma unroll 4
        for (int cc = 0; cc < 64; cc++) {
            int ci = ci0 + cc;
            float2 xv = xb[(size_t)ci * (HW / 2)];
            float2 pv = pb[(size_t)ci * (HW / 2)];
            float v0 = xv.x + pv.x, v1 = xv.y + pv.y;
            u64 s0 = pack2(v0, v0), s1 = pack2(v1, v1);
            const float4* wv = (const float4*)&buf[ci * 8];
            float4 w0 = wv[0], w1 = wv[1];
            u64 wp0 = pack2(w0.x, w0.y), wp1 = pack2(w0.z, w0.w);
            u64 wp2 = pack2(w1.x, w1.y), wp3 = pack2(w1.z, w1.w);
            fma2(a0[0], wp0, s0); fma2(a0[1], wp1, s0);
            fma2(a0[2], wp2, s0); fma2(a0[3], wp3, s0);
            fma2(a1[0], wp0, s1); fma2(a1[1], wp1, s1);
            fma2(a1[2], wp2, s1); fma2(a1[3], wp3, s1);
        }
        float* red = buf + 4096;                 // 64 rows x 128, stride-1
        #pragma unroll
        for (int par = 0; par < 2; par++) {
            __syncthreads();
            #pragma unroll
            for (int hp = 0; hp < 4; hp++) {
                float2 f = unpack2(par == 0 ? a0[hp] : a1[hp]);
                red[(slab * 8 + hp * 2)     * 128 + tl] = f.x;
                red[(slab * 8 + hp * 2 + 1) * 128 + tl] = f.y;
            }
            __syncthreads();
            int h2 = tid >> 7, tl2 = tid & 127;
            float s = 0.0f;
            #pragma unroll
            for (int q = 0; q < 8; q++) s += red[(q * 8 + h2) * 128 + tl2];
            g_p[((size_t)b * NH + h2) * T + t0 + 2 * tl2 + par + 1] = s;
        }
        __syncthreads();
    }
    GBAR();

    // ---- Phase 5 -----------------------------------------------------------
    {
        int grp  = warp >> 4;
        int row  = bid * 2 + grp;
        int tid2 = tid & 511;
        int lw   = warp & 15;
        bool act = row < B * NH;
        const float* p = g_p + (size_t)row * T;
        float v0 = act ? p[tid2]        : -1e30f;
        float v1 = act ? p[tid2 + 512]  : -1e30f;
        float v2 = (act && tid2 == 0) ? p[1024] : -1e30f;
        float m = fmaxf(fmaxf(v0, v1), v2);
        #pragma unroll
        for (int o = 16; o; o >>= 1) m = fmaxf(m, __shfl_xor_sync(0xffffffffu, m, o));
        if (lane == 0) buf[grp * 16 + lw] = m;
        __syncthreads();
        float M = buf[grp * 16];
        #pragma unroll
        for (int w = 1; w < 16; w++) M = fmaxf(M, buf[grp * 16 + w]);
        __syncthreads();
        float e0 = __expf(v0 - M), e1 = __expf(v1 - M);
        float e2 = (act && tid2 == 0) ? __expf(v2 - M) : 0.0f;
        float s = wred(e0 + e1 + e2);
        if (lane == 0) buf[grp * 16 + lw] = s;
        __syncthreads();
        float S = 0.0f;
        #pragma unroll
        for (int w = 0; w < 16; w++) S += buf[grp * 16 + w];
        float inv = 1.0f / S;
        if (act) {
            if (tid2 == 0) {
                g_p0[row] = e0 * inv;
                g_ps[(size_t)row * HW + 1023] = e2 * inv;
            } else {
                g_ps[(size_t)row * HW + tid2 - 1] = e0 * inv;
            }
            g_ps[(size_t)row * HW + tid2 + 511] = e1 * inv;
        }
    }
}

// ===========================================================================
// K3 = P6 (y = p.xf) | P7 (W_v) | P8 (W_c -> out)
// ===========================================================================
__global__ void __launch_bounds__(1024, 1)
k_back(const float* __restrict__ x,
       const float* __restrict__ wqkv, const float* __restrict__ bqkv,
       const float* __restrict__ wc,  const float* __restrict__ bc,
       float* __restrict__ out) {
    __shared__ __align__(16) float buf[12288];
    const int tid = threadIdx.x;
    const int warp = tid >> 5, lane = tid & 31;
    const int bid = blockIdx.x, NB = gridDim.x;
    const int NW = NB * 32, gw = bid * 32 + warp;
    unsigned sense = g_sense;

    // ---- Phase 6 -----------------------------------------------------------
    {
        const int NIT = B * 8;               // (b, ci-group-of-64)
        int start = (int)(((long long)bid * NIT) / NB);
        int end   = (int)(((long long)(bid + 1) * NIT) / NB);
        int cur_b = -1;
        for (int it = start; it < end; it++) {
            int b = it >> 3, cig = it & 7;
            if (b != cur_b) {
                __syncthreads();
                const float4* src = (const float4*)(g_ps + (size_t)b * NH * HW);
                float4* dst = (float4*)buf;
                dst[tid] = src[tid];
                dst[tid + 1024] = src[tid + 1024];
                if (tid < NH) buf[8192 + tid] = g_p0[b * NH + tid];
                __syncthreads();
                cur_b = b;
            }
            int ci0 = cig * 64 + warp * 2;
            const float4* xr0 = (const float4*)(x + ((size_t)b * C + ci0) * HW);
            const float4* xr1 = xr0 + (HW / 4);
            const float4* pr0 = (const float4*)(g_poss + (size_t)ci0 * HW);
            const float4* pr1 = pr0 + (HW / 4);
            u64 acca[8], accc[8];
            #pragma unroll
            for (int h = 0; h < 8; h++) { acca[h] = 0ull; accc[h] = 0ull; }
            #pragma unroll
            for (int k = 0; k < 8; k++) {
                int i4 = lane + 32 * k;
                float4 xa = xr0[i4], pa = pr0[i4];
                float4 xc = xr1[i4], pc = pr1[i4];
                u64 va01 = add2(pack2(xa.x, xa.y), pack2(pa.x, pa.y));
                u64 va23 = add2(pack2(xa.z, xa.w), pack2(pa.z, pa.w));
                u64 vc01 = add2(pack2(xc.x, xc.y), pack2(pc.x, pc.y));
                u64 vc23 = add2(pack2(xc.z, xc.w), pack2(pc.z, pc.w));
                #pragma unroll
                for (int h = 0; h < 8; h++) {
                    float4 pv = ((const float4*)buf)[h * (HW / 4) + i4];
                    u64 p01 = pack2(pv.x, pv.y), p23 = pack2(pv.z, pv.w);
                    fma2(acca[h], p01, va01);
                    fma2(acca[h], p23, va23);
                    fma2(accc[h], p01, vc01);
                    fma2(accc[h], p23, vc23);
                }
            }
            float ra[8], rc[8];
            #pragma unroll
            for (int h = 0; h < 8; h++) {
                float2 fa = unpack2(acca[h]);
                float2 fc = unpack2(accc[h]);
                ra[h] = fa.x + fa.y;
                rc[h] = fc.x + fc.y;
            }
            if (lane == 0) {
                float va = g_x0[(size_t)b * C + ci0];
                float vc = g_x0[(size_t)b * C + ci0 + 1];
                #pragma unroll
                for (int h = 0; h < 8; h++) {
                    ra[h] += buf[8192 + h] * va;
                    rc[h] += buf[8192 + h] * vc;
                }
            }
            #pragma unroll
            for (int h = 0; h < 8; h++) {
                float r0 = wred(ra[h]);
                float r1 = wred(rc[h]);
                if (lane == 0) {
                    g_y[((size_t)b * NH + h) * C + ci0]     = r0;
                    g_y[((size_t)b * NH + h) * C + ci0 + 1] = r1;
                }
            }
        }
    }
    GBAR();

    // ---- Phase 7 -----------------------------------------------------------
    for (int it = gw; it < C * 4; it += NW) {
        int c = it >> 2, bg = it & 3, h = c >> 6;
        const float4* w = (const float4*)(wqkv + (size_t)(2 * C + c) * C);
        float4 wr[4];
        #pragma unroll
        for (int k = 0; k < 4; k++) wr[k] = w[lane + 32 * k];
        float bv = bqkv[2 * C + c];
        #pragma unroll
        for (int j = 0; j < 8; j++) {
            int b = bg * 8 + j;
            const float4* y = (const float4*)(g_y + ((size_t)b * NH + h) * C);
            float acc = 0.0f;
            #pragma unroll
            for (int k = 0; k < 4; k++) {
                float4 d = y[lane + 32 * k];
                acc += wr[k].x * d.x + wr[k].y * d.y + wr[k].z * d.z + wr[k].w * d.w;
            }
            acc = wred(acc);
            if (lane == 0) g_a[b * C + c] = acc + bv;
        }
    }
    GBAR();

    // ---- Phase 8 -----------------------------------------------------------
    for (int it = gw; it < C * 4; it += NW) {
        int o = it >> 2, bg = it & 3;
        const float4* w = (const float4*)(wc + (size_t)o * C);
        float4 wr[4];
        #pragma unroll
        for (int k = 0; k < 4; k++) wr[k] = w[lane + 32 * k];
        float bo = bc[o];
        #pragma unroll
        for (int j = 0; j < 8; j++) {
            int b = bg * 8 + j;
            const float4* a = (const float4*)(g_a + (size_t)b * C);
            float acc = 0.0f;
            #pragma unroll
            for (int k = 0; k < 4; k++) {
                float4 d = a[lane + 32 * k];
                acc += wr[k].x * d.x + wr[k].y * d.y + wr[k].z * d.z + wr[k].w * d.w;
            }
            acc = wred(acc);
            if (lane == 0) out[b * C + o] = acc + bo;
        }
    }
}

// ---------------------------------------------------------------------------
extern "C" void kernel_launch(void* const* d_in, const int* in_sizes, int n_in,
                              void* d_out, int out_size) {
    const float* x    = (const float*)d_in[0];
    const float* pos  = (const float*)d_in[1];
    const float* wqkv = (const float*)d_in[2];
    const float* bqkv = (const float*)d_in[3];
    const float* wc   = (const float*)d_in[4];
    const float* bc   = (const float*)d_in[5];
    float* out = (float*)d_out;

    int nsm = 0;
    cudaDeviceGetAttribute(&nsm, cudaDevAttrMultiProcessorCount, 0);
    if (nsm <= 0) nsm = 148;
    k_front<<<nsm, 1024>>>(x, pos, wqkv, bqkv);
    k_mid  <<<nsm, 1024>>>(x);
    k_back <<<nsm, 1024>>>(x, wqkv, bqkv, wc, bc, out);
}